// round 13
// baseline (speedup 1.0000x reference)
#include <cuda_runtime.h>
#include <cuda_bf16.h>
#include <cstdint>
#include <math.h>

// ---------------------------------------------------------------------------
// SwinTLayer: B=4, H=64, W=128, C=512, F=1024, NH=8, hd=64, WS=4, SS=2
// bf16 HMMA (m16n8k16); fp32 accum, fp32 LN/softmax/GELU/residual.
// R8 GEMM config + interleaved cp.async; attention with hoisted V loads.
// ---------------------------------------------------------------------------

#define BATCH   4
#define IMH     64
#define IMW     128
#define CDIM    512
#define LTOK    (IMH*IMW)            // 8192
#define NHEADS  8
#define HDIM    64
#define NWINDOWS 2048
#define ROWS    (NWINDOWS*16)         // 32768
#define FDIM    1024

typedef __nv_bfloat16 bf16;

// Scratch (device globals; cudaMalloc forbidden)
__device__ __align__(1024) bf16  g_xw [ (size_t)ROWS*CDIM ];
__device__ __align__(1024) bf16  g_qkv[ (size_t)ROWS*3*CDIM ];
__device__ __align__(1024) bf16  g_ow [ (size_t)ROWS*CDIM ];
__device__ __align__(1024) float g_x2 [ (size_t)ROWS*CDIM ];   // residual, fp32
__device__ __align__(1024) bf16  g_h2 [ (size_t)ROWS*CDIM ];
__device__ __align__(1024) bf16  g_m1 [ (size_t)ROWS*FDIM ];
// bf16 weight copies
__device__ __align__(1024) bf16 g_wqkv[ 1536*512 ];
__device__ __align__(1024) bf16 g_wproj[ 512*512 ];
__device__ __align__(1024) bf16 g_w1  [ 1024*512 ];
__device__ __align__(1024) bf16 g_w2  [ 512*1024 ];

// ---------------------------------------------------------------------------
// helpers
// ---------------------------------------------------------------------------
__device__ __forceinline__ uint32_t smem_u32(const void* p) {
    return (uint32_t)__cvta_generic_to_shared(p);
}

__device__ __forceinline__ uint32_t bf2(float lo, float hi) {
    __nv_bfloat162 t = __floats2bfloat162_rn(lo, hi);
    return *reinterpret_cast<uint32_t*>(&t);
}
__device__ __forceinline__ uint32_t packh(bf16 lo, bf16 hi) {
    __nv_bfloat162 t(lo, hi);
    return *reinterpret_cast<uint32_t*>(&t);
}

#define CP_ASYNC16(dst, src) \
    asm volatile("cp.async.cg.shared.global [%0], [%1], 16;" :: "r"(dst), "l"(src))
#define CP_COMMIT()  asm volatile("cp.async.commit_group;")
#define CP_WAIT1()   asm volatile("cp.async.wait_group 1;")

// m16n8k16 bf16 HMMA (legacy warp path; valid on plain sm_103 target)
__device__ __forceinline__ void hmma_bf16(float* c,
                                          uint32_t a0, uint32_t a1, uint32_t a2, uint32_t a3,
                                          uint32_t b0, uint32_t b1)
{
    asm volatile(
        "mma.sync.aligned.m16n8k16.row.col.f32.bf16.bf16.f32 "
        "{%0,%1,%2,%3}, {%4,%5,%6,%7}, {%8,%9}, {%0,%1,%2,%3};"
        : "+f"(c[0]), "+f"(c[1]), "+f"(c[2]), "+f"(c[3])
        : "r"(a0), "r"(a1), "r"(a2), "r"(a3), "r"(b0), "r"(b1));
}

__device__ __forceinline__ void ldsm4(uint32_t& r0, uint32_t& r1,
                                      uint32_t& r2, uint32_t& r3, uint32_t addr)
{
    asm volatile("ldmatrix.sync.aligned.m8n8.x4.shared.b16 {%0,%1,%2,%3}, [%4];"
                 : "=r"(r0), "=r"(r1), "=r"(r2), "=r"(r3) : "r"(addr));
}

// window-row -> token-row map (shift + window partition; same gather/scatter)
__device__ __forceinline__ int swin_token(int r)
{
    int win   = r >> 4;
    int n     = r & 15;
    int b     = win >> 9;
    int local = win & 511;
    int wi    = local >> 5;
    int wj    = local & 31;
    int h     = (wi * 4 + (n >> 2) + 2) & (IMH - 1);
    int w     = (wj * 4 + (n & 3) + 2) & (IMW - 1);
    return b * LTOK + h * IMW + w;
}

// ---------------------------------------------------------------------------
// weight rounding to bf16 (rne)
// ---------------------------------------------------------------------------
__global__ void round_w_kernel(const float* __restrict__ a, const float* __restrict__ b,
                               const float* __restrict__ c, const float* __restrict__ d)
{
    int i = blockIdx.x * blockDim.x + threadIdx.x;
    int stride = gridDim.x * blockDim.x;
    for (int t = i; t < 1536*512; t += stride) g_wqkv[t]  = __float2bfloat16_rn(a[t]);
    for (int t = i; t < 512*512;  t += stride) g_wproj[t] = __float2bfloat16_rn(b[t]);
    for (int t = i; t < 1024*512; t += stride) g_w1[t]    = __float2bfloat16_rn(c[t]);
    for (int t = i; t < 512*1024; t += stride) g_w2[t]    = __float2bfloat16_rn(d[t]);
}

// ---------------------------------------------------------------------------
// LayerNorm (C=512), 128 threads, float4/thread, bf16 output.
// GATHER: swin gather from x (LN1 + shift + window partition).
// ---------------------------------------------------------------------------
template <bool GATHER>
__global__ void ln_kernel(const float* __restrict__ src,
                          const float* __restrict__ gamma,
                          const float* __restrict__ beta,
                          bf16* __restrict__ dst)
{
    int r    = blockIdx.x;
    int srow = GATHER ? swin_token(r) : r;
    float4 v = ((const float4*)(src + (size_t)srow * CDIM))[threadIdx.x];

    float s  = v.x + v.y + v.z + v.w;
    float sq = v.x*v.x + v.y*v.y + v.z*v.z + v.w*v.w;
    #pragma unroll
    for (int o = 16; o; o >>= 1) {
        s  += __shfl_xor_sync(0xffffffffu, s,  o);
        sq += __shfl_xor_sync(0xffffffffu, sq, o);
    }
    __shared__ float ss[4], ssq[4];
    int warp = threadIdx.x >> 5;
    if ((threadIdx.x & 31) == 0) { ss[warp] = s; ssq[warp] = sq; }
    __syncthreads();
    s  = ss[0] + ss[1] + ss[2] + ss[3];
    sq = ssq[0] + ssq[1] + ssq[2] + ssq[3];

    float mean = s * (1.0f / CDIM);
    float var  = sq * (1.0f / CDIM) - mean * mean;
    float rstd = rsqrtf(var + 1e-5f);

    float4 gv = ((const float4*)gamma)[threadIdx.x];
    float4 bv = ((const float4*)beta)[threadIdx.x];
    uint2 o;
    o.x = bf2((v.x - mean) * rstd * gv.x + bv.x, (v.y - mean) * rstd * gv.y + bv.y);
    o.y = bf2((v.z - mean) * rstd * gv.z + bv.z, (v.w - mean) * rstd * gv.w + bv.w);
    ((uint2*)(dst + (size_t)r * CDIM))[threadIdx.x] = o;
}

// ---------------------------------------------------------------------------
// bf16 HMMA GEMM: C[M,N] = A[M,K] @ B[N,K]^T (+bias, epilogue).
// CTA 128x128, BK=64 bf16 (128B/row), 128 threads (4 warps, 64x64 each),
// 3-stage cp.async (96KB -> 2 CTAs/SM), XOR swizzle, ldmatrix.x4 fragments.
// cp.async for slice ks+2 is interleaved across the 4 kt sub-iterations
// (4 per thread per kt) to avoid LSU issue bursts.
// EPI: 0 bias->bf16 | 1 bias+GELU->bf16 | 2 bias+aux->fp32 | 3 bias+swin scatter+aux->fp32
// ---------------------------------------------------------------------------
#define BM 128
#define BN 128
#define BKE 64                                   // K elements per slice
#define NSTAGES 3
#define STAGE_BYTES ((BM + BN) * BKE * 2)        // 32768
#define DYN_BYTES   (NSTAGES * STAGE_BYTES)      // 98304

template <int EPI>
__global__ void __launch_bounds__(128, 2)
mma_gemm(const bf16* __restrict__ A, const bf16* __restrict__ Bm,
         const float* __restrict__ bias, const float* __restrict__ aux,
         void* __restrict__ Cv, int Nn, int K)
{
    extern __shared__ char dyn[];
    uint32_t smem_base = smem_u32(dyn);

    int tid  = threadIdx.x;
    int wid  = tid >> 5;
    int lane = tid & 31;
    int rA   = lane >> 2;       // 0..7 (acc layout)
    int cA   = lane & 3;        // 0..3

    int m0 = (wid & 1) * 64;
    int n0 = (wid >> 1) * 64;

    int row0 = blockIdx.y * BM;
    int col0 = blockIdx.x * BN;
    int S    = K >> 6;          // K-slices of 64 bf16

    const bf16* Abase = A  + (size_t)row0 * K;
    const bf16* Bbase = Bm + (size_t)col0 * K;

    uint32_t lxor = (uint32_t)(lane & 7);
    uint32_t arow = (uint32_t)(m0 + (lane & 15));
    uint32_t ac0  = (uint32_t)(lane >> 4);
    uint32_t brow = (uint32_t)(n0 + ((lane >> 4) << 3) + (lane & 7));
    uint32_t bc0  = (uint32_t)((lane >> 3) & 1);

    // full-slice loader (prologue): 16 cp.async per thread
    auto load_slice = [&](int ks, int st) {
        uint32_t sA = smem_base + st * STAGE_BYTES;
        uint32_t sB = sA + BM * 128;
        const bf16* Ap = Abase + ks * BKE;
        const bf16* Bp = Bbase + ks * BKE;
        #pragma unroll
        for (int p = 0; p < 8; p++) {
            int idx = p * 128 + tid;
            int row = idx >> 3, ch = idx & 7;
            CP_ASYNC16(sA + (uint32_t)(row * 128 + ((ch ^ (row & 7)) * 16)),
                       Ap + (size_t)row * K + ch * 8);
        }
        #pragma unroll
        for (int p = 0; p < 8; p++) {
            int idx = p * 128 + tid;
            int row = idx >> 3, ch = idx & 7;
            CP_ASYNC16(sB + (uint32_t)(row * 128 + ((ch ^ (row & 7)) * 16)),
                       Bp + (size_t)row * K + ch * 8);
        }
    };

    // quarter-slice loader (mainloop): 4 cp.async per thread, part p in 0..3
    auto load_part = [&](const bf16* Ap, const bf16* Bp, uint32_t sA, uint32_t sB, int p) {
        #pragma unroll
        for (int q = 0; q < 2; q++) {
            int idx = (p * 2 + q) * 128 + tid;
            int row = idx >> 3, ch = idx & 7;
            CP_ASYNC16(sA + (uint32_t)(row * 128 + ((ch ^ (row & 7)) * 16)),
                       Ap + (size_t)row * K + ch * 8);
        }
        #pragma unroll
        for (int q = 0; q < 2; q++) {
            int idx = (p * 2 + q) * 128 + tid;
            int row = idx >> 3, ch = idx & 7;
            CP_ASYNC16(sB + (uint32_t)(row * 128 + ((ch ^ (row & 7)) * 16)),
                       Bp + (size_t)row * K + ch * 8);
        }
    };

    float acc[4][8][4];
    #pragma unroll
    for (int i = 0; i < 4; i++)
        #pragma unroll
        for (int j = 0; j < 8; j++)
            #pragma unroll
            for (int q = 0; q < 4; q++) acc[i][j][q] = 0.0f;

    load_slice(0, 0); CP_COMMIT();
    load_slice(1, 1); CP_COMMIT();

    for (int ks = 0; ks < S; ks++) {
        int st = ks % NSTAGES;
        CP_WAIT1();
        __syncthreads();

        bool doLoad = (ks + 2 < S);
        int pst = (ks + 2) % NSTAGES;
        const bf16* Ap = Abase + (ks + 2) * BKE;
        const bf16* Bp = Bbase + (ks + 2) * BKE;
        uint32_t psA = smem_base + pst * STAGE_BYTES;
        uint32_t psB = psA + BM * 128;

        uint32_t sA = smem_base + st * STAGE_BYTES;
        uint32_t sB = sA + BM * 128;

        #pragma unroll
        for (int kt = 0; kt < 4; kt++) {               // 4 x k16 per slice
            if (doLoad) load_part(Ap, Bp, psA, psB, kt);

            uint32_t af[4][4];
            #pragma unroll
            for (int mt = 0; mt < 4; mt++) {
                uint32_t row = arow + mt * 16;
                uint32_t ch  = (uint32_t)(kt * 2) + ac0;
                ldsm4(af[mt][0], af[mt][1], af[mt][2], af[mt][3],
                      sA + row * 128 + ((ch ^ lxor) * 16));
            }
            uint32_t bf[8][2];
            #pragma unroll
            for (int ntp = 0; ntp < 4; ntp++) {
                uint32_t row = brow + ntp * 16;
                uint32_t ch  = (uint32_t)(kt * 2) + bc0;
                ldsm4(bf[2*ntp][0], bf[2*ntp][1], bf[2*ntp+1][0], bf[2*ntp+1][1],
                      sB + row * 128 + ((ch ^ lxor) * 16));
            }
            #pragma unroll
            for (int mt = 0; mt < 4; mt++)
                #pragma unroll
                for (int nt = 0; nt < 8; nt++)
                    hmma_bf16(acc[mt][nt], af[mt][0], af[mt][1], af[mt][2], af[mt][3],
                              bf[nt][0], bf[nt][1]);
        }
        CP_COMMIT();
    }

    // ---- epilogue ----
    #pragma unroll
    for (int mt = 0; mt < 4; mt++) {
        #pragma unroll
        for (int half = 0; half < 2; half++) {
            int grow = row0 + m0 + mt * 16 + half * 8 + rA;
            int tt   = (EPI == 3) ? swin_token(grow) : grow;
            #pragma unroll
            for (int nt = 0; nt < 8; nt++) {
                int col = col0 + n0 + nt * 8 + cA * 2;
                float v0 = acc[mt][nt][half * 2 + 0] + bias[col];
                float v1 = acc[mt][nt][half * 2 + 1] + bias[col + 1];
                if (EPI == 0) {
                    *(uint32_t*)((bf16*)Cv + (size_t)grow * Nn + col) = bf2(v0, v1);
                } else if (EPI == 1) {
                    v0 = 0.5f * v0 * (1.0f + erff(v0 * 0.70710678118654752f));
                    v1 = 0.5f * v1 * (1.0f + erff(v1 * 0.70710678118654752f));
                    *(uint32_t*)((bf16*)Cv + (size_t)grow * Nn + col) = bf2(v0, v1);
                } else if (EPI == 2) {
                    float2 ax = *(const float2*)(aux + (size_t)grow * Nn + col);
                    *(float2*)((float*)Cv + (size_t)grow * Nn + col) =
                        make_float2(v0 + ax.x, v1 + ax.y);
                } else {
                    float2 ax = *(const float2*)(aux + (size_t)tt * CDIM + col);
                    *(float2*)((float*)Cv + (size_t)tt * CDIM + col) =
                        make_float2(v0 + ax.x, v1 + ax.y);
                }
            }
        }
    }
}

// ---------------------------------------------------------------------------
// Windowed attention via bf16 HMMA: one warp per (window, head).
// Block = 256 threads = 8 warps = 8 heads of one window. Grid = 2048.
// V-operand and rpb loads hoisted above QK^T so their latency hides under
// the QK MMAs + softmax instead of being exposed before PV.
// ---------------------------------------------------------------------------
__global__ void __launch_bounds__(256) attn_mma(const float* __restrict__ rpb)
{
    int win  = blockIdx.x;
    int head = threadIdx.x >> 5;
    int lane = threadIdx.x & 31;
    int rhi  = lane >> 2;       // 0..7
    int rlo  = lane & 3;        // 0..3

    const bf16* qb = g_qkv + (size_t)(win * 16) * 1536 + head * 64;
    const bf16* kb = qb + 512;
    const bf16* vb = qb + 1024;

    int i0 = rhi, i1 = rhi + 8;

    // ---- hoisted PV b-fragments: independent of P, issued first ----
    uint32_t vb0[8], vb1[8];
    #pragma unroll
    for (int nt = 0; nt < 8; nt++) {
        int colb = nt * 8 + rhi;
        vb0[nt] = packh(vb[(size_t)(2 * rlo) * 1536 + colb],
                        vb[(size_t)(2 * rlo + 1) * 1536 + colb]);
        vb1[nt] = packh(vb[(size_t)(8 + 2 * rlo) * 1536 + colb],
                        vb[(size_t)(9 + 2 * rlo) * 1536 + colb]);
    }

    // ---- hoisted rel-pos bias loads ----
    float rb[2][4];
    #pragma unroll
    for (int nt = 0; nt < 2; nt++)
        #pragma unroll
        for (int q = 0; q < 4; q++) {
            int i = (q < 2) ? i0 : i1;
            int j = nt * 8 + 2 * rlo + (q & 1);
            int idx = ((i >> 2) - (j >> 2) + 3) * 7 + ((i & 3) - (j & 3) + 3);
            rb[nt][q] = __ldg(rpb + idx * NHEADS + head);
        }

    int local = win & 511;
    int wi = local >> 5, wj = local & 31;

    auto reg_of = [&](int tok) {
        int hs = wi * 4 + (tok >> 2);
        int ws = wj * 4 + (tok & 3);
        int rh = hs < (IMH - 4) ? 0 : (hs < (IMH - 2) ? 1 : 2);
        int rw = ws < (IMW - 4) ? 0 : (ws < (IMW - 2) ? 1 : 2);
        return rh * 3 + rw;
    };

    const __nv_bfloat162 scl = __float2bfloat162_rn(0.125f);   // exact

    auto ldq = [&](const bf16* p) {
        __nv_bfloat162 t = __hmul2(*(const __nv_bfloat162*)p, scl);
        return *reinterpret_cast<uint32_t*>(&t);
    };

    // ---- S = (Q*scale) K^T : m16n8k16, 4 k-steps, 2 n-tiles ----
    float s0[4] = {0,0,0,0}, s1[4] = {0,0,0,0};
    #pragma unroll
    for (int kt = 0; kt < 4; kt++) {
        int c = kt * 16 + 2 * rlo;
        uint32_t a0 = ldq(qb + (size_t)i0 * 1536 + c);
        uint32_t a1 = ldq(qb + (size_t)i1 * 1536 + c);
        uint32_t a2 = ldq(qb + (size_t)i0 * 1536 + c + 8);
        uint32_t a3 = ldq(qb + (size_t)i1 * 1536 + c + 8);
        uint32_t b0 = *(const uint32_t*)(kb + (size_t)rhi * 1536 + c);
        uint32_t b1 = *(const uint32_t*)(kb + (size_t)rhi * 1536 + c + 8);
        hmma_bf16(s0, a0, a1, a2, a3, b0, b1);
        b0 = *(const uint32_t*)(kb + (size_t)(rhi + 8) * 1536 + c);
        b1 = *(const uint32_t*)(kb + (size_t)(rhi + 8) * 1536 + c + 8);
        hmma_bf16(s1, a0, a1, a2, a3, b0, b1);
    }

    // ---- + rel-pos bias + shift mask ----
    int ri0 = reg_of(i0), ri1 = reg_of(i1);
    #pragma unroll
    for (int nt = 0; nt < 2; nt++) {
        float* s = nt ? s1 : s0;
        #pragma unroll
        for (int q = 0; q < 4; q++) {
            int i  = (q < 2) ? i0 : i1;
            int ri = (q < 2) ? ri0 : ri1;
            int j  = nt * 8 + 2 * rlo + (q & 1);
            s[q] += rb[nt][q] + ((ri != reg_of(j)) ? -100.0f : 0.0f);
        }
    }

    // ---- softmax (rows i0: regs 0,1 ; i1: regs 2,3 ; quad reduce) ----
    float m0 = fmaxf(fmaxf(s0[0], s0[1]), fmaxf(s1[0], s1[1]));
    float m1 = fmaxf(fmaxf(s0[2], s0[3]), fmaxf(s1[2], s1[3]));
    m0 = fmaxf(m0, __shfl_xor_sync(~0u, m0, 1));
    m0 = fmaxf(m0, __shfl_xor_sync(~0u, m0, 2));
    m1 = fmaxf(m1, __shfl_xor_sync(~0u, m1, 1));
    m1 = fmaxf(m1, __shfl_xor_sync(~0u, m1, 2));
    s0[0] = __expf(s0[0] - m0); s0[1] = __expf(s0[1] - m0);
    s1[0] = __expf(s1[0] - m0); s1[1] = __expf(s1[1] - m0);
    s0[2] = __expf(s0[2] - m1); s0[3] = __expf(s0[3] - m1);
    s1[2] = __expf(s1[2] - m1); s1[3] = __expf(s1[3] - m1);
    float t0 = s0[0] + s0[1] + s1[0] + s1[1];
    float t1 = s0[2] + s0[3] + s1[2] + s1[3];
    t0 += __shfl_xor_sync(~0u, t0, 1); t0 += __shfl_xor_sync(~0u, t0, 2);
    t1 += __shfl_xor_sync(~0u, t1, 1); t1 += __shfl_xor_sync(~0u, t1, 2);
    float inv0 = 1.0f / t0, inv1 = 1.0f / t1;

    // ---- P in A-fragment layout directly (acc pairs == a-frag pairs) ----
    uint32_t pa0 = bf2(s0[0] * inv0, s0[1] * inv0);   // P[i0][j 0-7]
    uint32_t pa1 = bf2(s0[2] * inv1, s0[3] * inv1);   // P[i1][j 0-7]
    uint32_t pa2 = bf2(s1[0] * inv0, s1[1] * inv0);   // P[i0][j 8-15]
    uint32_t pa3 = bf2(s1[2] * inv1, s1[3] * inv1);   // P[i1][j 8-15]

    // ---- O = P V : one k16 MMA per 8-col tile of hd=64 ----
    bf16* ob = g_ow + (size_t)(win * 16) * CDIM + head * 64;
    #pragma unroll
    for (int nt = 0; nt < 8; nt++) {
        float o[4] = {0, 0, 0, 0};
        hmma_bf16(o, pa0, pa1, pa2, pa3, vb0[nt], vb1[nt]);
        int col = nt * 8 + 2 * rlo;
        *(uint32_t*)(ob + (size_t)i0 * CDIM + col) = bf2(o[0], o[1]);
        *(uint32_t*)(ob + (size_t)i1 * CDIM + col) = bf2(o[2], o[3]);
    }
}

// ---------------------------------------------------------------------------
// Launch
// ---------------------------------------------------------------------------
extern "C" void kernel_launch(void* const* d_in, const int* in_sizes, int n_in,
                              void* d_out, int out_size)
{
    const float* x      = (const float*)d_in[0];
    const float* g1     = (const float*)d_in[1];
    const float* beta1  = (const float*)d_in[2];
    const float* w_qkv  = (const float*)d_in[3];
    const float* b_qkv  = (const float*)d_in[4];
    const float* rpb    = (const float*)d_in[5];
    const float* w_proj = (const float*)d_in[6];
    const float* b_proj = (const float*)d_in[7];
    const float* g2     = (const float*)d_in[8];
    const float* beta2  = (const float*)d_in[9];
    const float* w1     = (const float*)d_in[10];
    const float* b1     = (const float*)d_in[11];
    const float* w2     = (const float*)d_in[12];
    const float* b2     = (const float*)d_in[13];
    float* out = (float*)d_out;

    bf16 *xw, *qkv, *ow, *h2, *m1, *wq, *wp, *wa, *wb;
    float *x2;
    cudaGetSymbolAddress((void**)&xw,  g_xw);
    cudaGetSymbolAddress((void**)&qkv, g_qkv);
    cudaGetSymbolAddress((void**)&ow,  g_ow);
    cudaGetSymbolAddress((void**)&x2,  g_x2);
    cudaGetSymbolAddress((void**)&h2,  g_h2);
    cudaGetSymbolAddress((void**)&m1,  g_m1);
    cudaGetSymbolAddress((void**)&wq,  g_wqkv);
    cudaGetSymbolAddress((void**)&wp,  g_wproj);
    cudaGetSymbolAddress((void**)&wa,  g_w1);
    cudaGetSymbolAddress((void**)&wb,  g_w2);

    cudaFuncSetAttribute(mma_gemm<0>, cudaFuncAttributeMaxDynamicSharedMemorySize, DYN_BYTES);
    cudaFuncSetAttribute(mma_gemm<1>, cudaFuncAttributeMaxDynamicSharedMemorySize, DYN_BYTES);
    cudaFuncSetAttribute(mma_gemm<2>, cudaFuncAttributeMaxDynamicSharedMemorySize, DYN_BYTES);
    cudaFuncSetAttribute(mma_gemm<3>, cudaFuncAttributeMaxDynamicSharedMemorySize, DYN_BYTES);

    // 0. weights -> bf16
    round_w_kernel<<<592, 256>>>(w_qkv, w_proj, w1, w2);

    // 1. LN1 + shift + window partition -> g_xw (bf16)
    ln_kernel<true><<<ROWS, 128>>>(x, g1, beta1, xw);

    // 2. QKV: [32768,1536] = xw @ wqkv^T  (bf16 out)
    mma_gemm<0><<<dim3(1536/BN, ROWS/BM), 128, DYN_BYTES>>>(xw, wq, b_qkv, nullptr, qkv, 1536, 512);

    // 3. attention -> g_ow (bf16)
    attn_mma<<<NWINDOWS, 256>>>(rpb);

    // 4. proj + window reverse + unshift + residual(x) -> g_x2 (fp32)
    mma_gemm<3><<<dim3(512/BN, ROWS/BM), 128, DYN_BYTES>>>(ow, wp, b_proj, x, x2, 512, 512);

    // 5. LN2 -> g_h2 (bf16)
    ln_kernel<false><<<ROWS, 128>>>(x2, g2, beta2, h2);

    // 6. FC1 + GELU -> g_m1 (bf16)
    mma_gemm<1><<<dim3(1024/BN, ROWS/BM), 128, DYN_BYTES>>>(h2, wa, b1, nullptr, m1, 1024, 512);

    // 7. FC2 + residual(g_x2) -> out (fp32)
    mma_gemm<2><<<dim3(512/BN, ROWS/BM), 128, DYN_BYTES>>>(m1, wb, b2, x2, out, 512, 1024);
}

// round 15
// speedup vs baseline: 1.0196x; 1.0196x over previous
#include <cuda_runtime.h>
#include <cuda_bf16.h>
#include <cstdint>
#include <math.h>

// ---------------------------------------------------------------------------
// SwinTLayer: B=4, H=64, W=128, C=512, F=1024, NH=8, hd=64, WS=4, SS=2
// bf16 HMMA (m16n8k16); fp32 accum, fp32 LN/softmax/GELU/residual.
// GEMM: R8 burst-loader config (empirical optimum).
// Attention: hoisted V/rpb loads (R13 win).
// ---------------------------------------------------------------------------

#define BATCH   4
#define IMH     64
#define IMW     128
#define CDIM    512
#define LTOK    (IMH*IMW)            // 8192
#define NHEADS  8
#define HDIM    64
#define NWINDOWS 2048
#define ROWS    (NWINDOWS*16)         // 32768
#define FDIM    1024

typedef __nv_bfloat16 bf16;

// Scratch (device globals; cudaMalloc forbidden)
__device__ __align__(1024) bf16  g_xw [ (size_t)ROWS*CDIM ];
__device__ __align__(1024) bf16  g_qkv[ (size_t)ROWS*3*CDIM ];
__device__ __align__(1024) bf16  g_ow [ (size_t)ROWS*CDIM ];
__device__ __align__(1024) float g_x2 [ (size_t)ROWS*CDIM ];   // residual, fp32
__device__ __align__(1024) bf16  g_h2 [ (size_t)ROWS*CDIM ];
__device__ __align__(1024) bf16  g_m1 [ (size_t)ROWS*FDIM ];
// bf16 weight copies
__device__ __align__(1024) bf16 g_wqkv[ 1536*512 ];
__device__ __align__(1024) bf16 g_wproj[ 512*512 ];
__device__ __align__(1024) bf16 g_w1  [ 1024*512 ];
__device__ __align__(1024) bf16 g_w2  [ 512*1024 ];

// ---------------------------------------------------------------------------
// helpers
// ---------------------------------------------------------------------------
__device__ __forceinline__ uint32_t smem_u32(const void* p) {
    return (uint32_t)__cvta_generic_to_shared(p);
}

__device__ __forceinline__ uint32_t bf2(float lo, float hi) {
    __nv_bfloat162 t = __floats2bfloat162_rn(lo, hi);
    return *reinterpret_cast<uint32_t*>(&t);
}
__device__ __forceinline__ uint32_t packh(bf16 lo, bf16 hi) {
    __nv_bfloat162 t(lo, hi);
    return *reinterpret_cast<uint32_t*>(&t);
}

#define CP_ASYNC16(dst, src) \
    asm volatile("cp.async.cg.shared.global [%0], [%1], 16;" :: "r"(dst), "l"(src))
#define CP_COMMIT()  asm volatile("cp.async.commit_group;")
#define CP_WAIT1()   asm volatile("cp.async.wait_group 1;")

// m16n8k16 bf16 HMMA (legacy warp path; valid on plain sm_103 target)
__device__ __forceinline__ void hmma_bf16(float* c,
                                          uint32_t a0, uint32_t a1, uint32_t a2, uint32_t a3,
                                          uint32_t b0, uint32_t b1)
{
    asm volatile(
        "mma.sync.aligned.m16n8k16.row.col.f32.bf16.bf16.f32 "
        "{%0,%1,%2,%3}, {%4,%5,%6,%7}, {%8,%9}, {%0,%1,%2,%3};"
        : "+f"(c[0]), "+f"(c[1]), "+f"(c[2]), "+f"(c[3])
        : "r"(a0), "r"(a1), "r"(a2), "r"(a3), "r"(b0), "r"(b1));
}

__device__ __forceinline__ void ldsm4(uint32_t& r0, uint32_t& r1,
                                      uint32_t& r2, uint32_t& r3, uint32_t addr)
{
    asm volatile("ldmatrix.sync.aligned.m8n8.x4.shared.b16 {%0,%1,%2,%3}, [%4];"
                 : "=r"(r0), "=r"(r1), "=r"(r2), "=r"(r3) : "r"(addr));
}

// window-row -> token-row map (shift + window partition; same gather/scatter)
__device__ __forceinline__ int swin_token(int r)
{
    int win   = r >> 4;
    int n     = r & 15;
    int b     = win >> 9;
    int local = win & 511;
    int wi    = local >> 5;
    int wj    = local & 31;
    int h     = (wi * 4 + (n >> 2) + 2) & (IMH - 1);
    int w     = (wj * 4 + (n & 3) + 2) & (IMW - 1);
    return b * LTOK + h * IMW + w;
}

// ---------------------------------------------------------------------------
// weight rounding to bf16 (rne)
// ---------------------------------------------------------------------------
__global__ void round_w_kernel(const float* __restrict__ a, const float* __restrict__ b,
                               const float* __restrict__ c, const float* __restrict__ d)
{
    int i = blockIdx.x * blockDim.x + threadIdx.x;
    int stride = gridDim.x * blockDim.x;
    for (int t = i; t < 1536*512; t += stride) g_wqkv[t]  = __float2bfloat16_rn(a[t]);
    for (int t = i; t < 512*512;  t += stride) g_wproj[t] = __float2bfloat16_rn(b[t]);
    for (int t = i; t < 1024*512; t += stride) g_w1[t]    = __float2bfloat16_rn(c[t]);
    for (int t = i; t < 512*1024; t += stride) g_w2[t]    = __float2bfloat16_rn(d[t]);
}

// ---------------------------------------------------------------------------
// LayerNorm (C=512), 128 threads, float4/thread, bf16 output.
// GATHER: swin gather from x (LN1 + shift + window partition).
// ---------------------------------------------------------------------------
template <bool GATHER>
__global__ void ln_kernel(const float* __restrict__ src,
                          const float* __restrict__ gamma,
                          const float* __restrict__ beta,
                          bf16* __restrict__ dst)
{
    int r    = blockIdx.x;
    int srow = GATHER ? swin_token(r) : r;
    float4 v = ((const float4*)(src + (size_t)srow * CDIM))[threadIdx.x];

    float s  = v.x + v.y + v.z + v.w;
    float sq = v.x*v.x + v.y*v.y + v.z*v.z + v.w*v.w;
    #pragma unroll
    for (int o = 16; o; o >>= 1) {
        s  += __shfl_xor_sync(0xffffffffu, s,  o);
        sq += __shfl_xor_sync(0xffffffffu, sq, o);
    }
    __shared__ float ss[4], ssq[4];
    int warp = threadIdx.x >> 5;
    if ((threadIdx.x & 31) == 0) { ss[warp] = s; ssq[warp] = sq; }
    __syncthreads();
    s  = ss[0] + ss[1] + ss[2] + ss[3];
    sq = ssq[0] + ssq[1] + ssq[2] + ssq[3];

    float mean = s * (1.0f / CDIM);
    float var  = sq * (1.0f / CDIM) - mean * mean;
    float rstd = rsqrtf(var + 1e-5f);

    float4 gv = ((const float4*)gamma)[threadIdx.x];
    float4 bv = ((const float4*)beta)[threadIdx.x];
    uint2 o;
    o.x = bf2((v.x - mean) * rstd * gv.x + bv.x, (v.y - mean) * rstd * gv.y + bv.y);
    o.y = bf2((v.z - mean) * rstd * gv.z + bv.z, (v.w - mean) * rstd * gv.w + bv.w);
    ((uint2*)(dst + (size_t)r * CDIM))[threadIdx.x] = o;
}

// ---------------------------------------------------------------------------
// bf16 HMMA GEMM (R8 config): C[M,N] = A[M,K] @ B[N,K]^T (+bias, epilogue).
// CTA 128x128, BK=64 bf16 (128B/row), 128 threads (4 warps, 64x64 each),
// 3-stage cp.async (96KB -> 2 CTAs/SM), XOR swizzle, ldmatrix.x4 fragments.
// EPI: 0 bias->bf16 | 1 bias+GELU->bf16 | 2 bias+aux->fp32 | 3 bias+swin scatter+aux->fp32
// ---------------------------------------------------------------------------
#define BM 128
#define BN 128
#define BKE 64                                   // K elements per slice
#define NSTAGES 3
#define STAGE_BYTES ((BM + BN) * BKE * 2)        // 32768
#define DYN_BYTES   (NSTAGES * STAGE_BYTES)      // 98304

template <int EPI>
__global__ void __launch_bounds__(128, 2)
mma_gemm(const bf16* __restrict__ A, const bf16* __restrict__ Bm,
         const float* __restrict__ bias, const float* __restrict__ aux,
         void* __restrict__ Cv, int Nn, int K)
{
    extern __shared__ char dyn[];
    uint32_t smem_base = smem_u32(dyn);

    int tid  = threadIdx.x;
    int wid  = tid >> 5;
    int lane = tid & 31;
    int rA   = lane >> 2;       // 0..7 (acc layout)
    int cA   = lane & 3;        // 0..3

    int m0 = (wid & 1) * 64;
    int n0 = (wid >> 1) * 64;

    int row0 = blockIdx.y * BM;
    int col0 = blockIdx.x * BN;
    int S    = K >> 6;          // K-slices of 64 bf16

    const bf16* Abase = A  + (size_t)row0 * K;
    const bf16* Bbase = Bm + (size_t)col0 * K;

    uint32_t lxor = (uint32_t)(lane & 7);
    uint32_t arow = (uint32_t)(m0 + (lane & 15));
    uint32_t ac0  = (uint32_t)(lane >> 4);
    uint32_t brow = (uint32_t)(n0 + ((lane >> 4) << 3) + (lane & 7));
    uint32_t bc0  = (uint32_t)((lane >> 3) & 1);

    // ---- async tile loader: 16 cp.async (16B = 8 bf16) per thread/stage ----
    auto load_slice = [&](int ks, int st) {
        uint32_t sA = smem_base + st * STAGE_BYTES;
        uint32_t sB = sA + BM * 128;
        const bf16* Ap = Abase + ks * BKE;
        const bf16* Bp = Bbase + ks * BKE;
        #pragma unroll
        for (int p = 0; p < 8; p++) {                  // A: 1024 chunks
            int idx = p * 128 + tid;
            int row = idx >> 3, ch = idx & 7;
            CP_ASYNC16(sA + (uint32_t)(row * 128 + ((ch ^ (row & 7)) * 16)),
                       Ap + (size_t)row * K + ch * 8);
        }
        #pragma unroll
        for (int p = 0; p < 8; p++) {                  // B: 1024 chunks
            int idx = p * 128 + tid;
            int row = idx >> 3, ch = idx & 7;
            CP_ASYNC16(sB + (uint32_t)(row * 128 + ((ch ^ (row & 7)) * 16)),
                       Bp + (size_t)row * K + ch * 8);
        }
    };

    float acc[4][8][4];
    #pragma unroll
    for (int i = 0; i < 4; i++)
        #pragma unroll
        for (int j = 0; j < 8; j++)
            #pragma unroll
            for (int q = 0; q < 4; q++) acc[i][j][q] = 0.0f;

    load_slice(0, 0); CP_COMMIT();
    load_slice(1, 1); CP_COMMIT();

    for (int ks = 0; ks < S; ks++) {
        int st = ks % NSTAGES;
        CP_WAIT1();
        __syncthreads();

        if (ks + 2 < S) load_slice(ks + 2, (ks + 2) % NSTAGES);
        CP_COMMIT();

        uint32_t sA = smem_base + st * STAGE_BYTES;
        uint32_t sB = sA + BM * 128;

        #pragma unroll
        for (int kt = 0; kt < 4; kt++) {               // 4 x k16 per slice
            uint32_t af[4][4];
            #pragma unroll
            for (int mt = 0; mt < 4; mt++) {
                uint32_t row = arow + mt * 16;
                uint32_t ch  = (uint32_t)(kt * 2) + ac0;
                ldsm4(af[mt][0], af[mt][1], af[mt][2], af[mt][3],
                      sA + row * 128 + ((ch ^ lxor) * 16));
            }
            uint32_t bf[8][2];
            #pragma unroll
            for (int ntp = 0; ntp < 4; ntp++) {
                uint32_t row = brow + ntp * 16;
                uint32_t ch  = (uint32_t)(kt * 2) + bc0;
                ldsm4(bf[2*ntp][0], bf[2*ntp][1], bf[2*ntp+1][0], bf[2*ntp+1][1],
                      sB + row * 128 + ((ch ^ lxor) * 16));
            }
            #pragma unroll
            for (int mt = 0; mt < 4; mt++)
                #pragma unroll
                for (int nt = 0; nt < 8; nt++)
                    hmma_bf16(acc[mt][nt], af[mt][0], af[mt][1], af[mt][2], af[mt][3],
                              bf[nt][0], bf[nt][1]);
        }
    }

    // ---- epilogue ----
    #pragma unroll
    for (int mt = 0; mt < 4; mt++) {
        #pragma unroll
        for (int half = 0; half < 2; half++) {
            int grow = row0 + m0 + mt * 16 + half * 8 + rA;
            int tt   = (EPI == 3) ? swin_token(grow) : grow;
            #pragma unroll
            for (int nt = 0; nt < 8; nt++) {
                int col = col0 + n0 + nt * 8 + cA * 2;
                float v0 = acc[mt][nt][half * 2 + 0] + bias[col];
                float v1 = acc[mt][nt][half * 2 + 1] + bias[col + 1];
                if (EPI == 0) {
                    *(uint32_t*)((bf16*)Cv + (size_t)grow * Nn + col) = bf2(v0, v1);
                } else if (EPI == 1) {
                    v0 = 0.5f * v0 * (1.0f + erff(v0 * 0.70710678118654752f));
                    v1 = 0.5f * v1 * (1.0f + erff(v1 * 0.70710678118654752f));
                    *(uint32_t*)((bf16*)Cv + (size_t)grow * Nn + col) = bf2(v0, v1);
                } else if (EPI == 2) {
                    float2 ax = *(const float2*)(aux + (size_t)grow * Nn + col);
                    *(float2*)((float*)Cv + (size_t)grow * Nn + col) =
                        make_float2(v0 + ax.x, v1 + ax.y);
                } else {
                    float2 ax = *(const float2*)(aux + (size_t)tt * CDIM + col);
                    *(float2*)((float*)Cv + (size_t)tt * CDIM + col) =
                        make_float2(v0 + ax.x, v1 + ax.y);
                }
            }
        }
    }
}

// ---------------------------------------------------------------------------
// Windowed attention via bf16 HMMA: one warp per (window, head).
// Block = 256 threads = 8 warps = 8 heads of one window. Grid = 2048.
// V-operand and rpb loads hoisted above QK^T (latency hidden under QK+softmax).
// ---------------------------------------------------------------------------
__global__ void __launch_bounds__(256) attn_mma(const float* __restrict__ rpb)
{
    int win  = blockIdx.x;
    int head = threadIdx.x >> 5;
    int lane = threadIdx.x & 31;
    int rhi  = lane >> 2;       // 0..7
    int rlo  = lane & 3;        // 0..3

    const bf16* qb = g_qkv + (size_t)(win * 16) * 1536 + head * 64;
    const bf16* kb = qb + 512;
    const bf16* vb = qb + 1024;

    int i0 = rhi, i1 = rhi + 8;

    // ---- hoisted PV b-fragments: independent of P, issued first ----
    uint32_t vb0[8], vb1[8];
    #pragma unroll
    for (int nt = 0; nt < 8; nt++) {
        int colb = nt * 8 + rhi;
        vb0[nt] = packh(vb[(size_t)(2 * rlo) * 1536 + colb],
                        vb[(size_t)(2 * rlo + 1) * 1536 + colb]);
        vb1[nt] = packh(vb[(size_t)(8 + 2 * rlo) * 1536 + colb],
                        vb[(size_t)(9 + 2 * rlo) * 1536 + colb]);
    }

    // ---- hoisted rel-pos bias loads ----
    float rb[2][4];
    #pragma unroll
    for (int nt = 0; nt < 2; nt++)
        #pragma unroll
        for (int q = 0; q < 4; q++) {
            int i = (q < 2) ? i0 : i1;
            int j = nt * 8 + 2 * rlo + (q & 1);
            int idx = ((i >> 2) - (j >> 2) + 3) * 7 + ((i & 3) - (j & 3) + 3);
            rb[nt][q] = __ldg(rpb + idx * NHEADS + head);
        }

    int local = win & 511;
    int wi = local >> 5, wj = local & 31;

    auto reg_of = [&](int tok) {
        int hs = wi * 4 + (tok >> 2);
        int ws = wj * 4 + (tok & 3);
        int rh = hs < (IMH - 4) ? 0 : (hs < (IMH - 2) ? 1 : 2);
        int rw = ws < (IMW - 4) ? 0 : (ws < (IMW - 2) ? 1 : 2);
        return rh * 3 + rw;
    };

    const __nv_bfloat162 scl = __float2bfloat162_rn(0.125f);   // exact

    auto ldq = [&](const bf16* p) {
        __nv_bfloat162 t = __hmul2(*(const __nv_bfloat162*)p, scl);
        return *reinterpret_cast<uint32_t*>(&t);
    };

    // ---- S = (Q*scale) K^T : m16n8k16, 4 k-steps, 2 n-tiles ----
    float s0[4] = {0,0,0,0}, s1[4] = {0,0,0,0};
    #pragma unroll
    for (int kt = 0; kt < 4; kt++) {
        int c = kt * 16 + 2 * rlo;
        uint32_t a0 = ldq(qb + (size_t)i0 * 1536 + c);
        uint32_t a1 = ldq(qb + (size_t)i1 * 1536 + c);
        uint32_t a2 = ldq(qb + (size_t)i0 * 1536 + c + 8);
        uint32_t a3 = ldq(qb + (size_t)i1 * 1536 + c + 8);
        uint32_t b0 = *(const uint32_t*)(kb + (size_t)rhi * 1536 + c);
        uint32_t b1 = *(const uint32_t*)(kb + (size_t)rhi * 1536 + c + 8);
        hmma_bf16(s0, a0, a1, a2, a3, b0, b1);
        b0 = *(const uint32_t*)(kb + (size_t)(rhi + 8) * 1536 + c);
        b1 = *(const uint32_t*)(kb + (size_t)(rhi + 8) * 1536 + c + 8);
        hmma_bf16(s1, a0, a1, a2, a3, b0, b1);
    }

    // ---- + rel-pos bias + shift mask ----
    int ri0 = reg_of(i0), ri1 = reg_of(i1);
    #pragma unroll
    for (int nt = 0; nt < 2; nt++) {
        float* s = nt ? s1 : s0;
        #pragma unroll
        for (int q = 0; q < 4; q++) {
            int i  = (q < 2) ? i0 : i1;
            int ri = (q < 2) ? ri0 : ri1;
            int j  = nt * 8 + 2 * rlo + (q & 1);
            s[q] += rb[nt][q] + ((ri != reg_of(j)) ? -100.0f : 0.0f);
        }
    }

    // ---- softmax (rows i0: regs 0,1 ; i1: regs 2,3 ; quad reduce) ----
    float m0 = fmaxf(fmaxf(s0[0], s0[1]), fmaxf(s1[0], s1[1]));
    float m1 = fmaxf(fmaxf(s0[2], s0[3]), fmaxf(s1[2], s1[3]));
    m0 = fmaxf(m0, __shfl_xor_sync(~0u, m0, 1));
    m0 = fmaxf(m0, __shfl_xor_sync(~0u, m0, 2));
    m1 = fmaxf(m1, __shfl_xor_sync(~0u, m1, 1));
    m1 = fmaxf(m1, __shfl_xor_sync(~0u, m1, 2));
    s0[0] = __expf(s0[0] - m0); s0[1] = __expf(s0[1] - m0);
    s1[0] = __expf(s1[0] - m0); s1[1] = __expf(s1[1] - m0);
    s0[2] = __expf(s0[2] - m1); s0[3] = __expf(s0[3] - m1);
    s1[2] = __expf(s1[2] - m1); s1[3] = __expf(s1[3] - m1);
    float t0 = s0[0] + s0[1] + s1[0] + s1[1];
    float t1 = s0[2] + s0[3] + s1[2] + s1[3];
    t0 += __shfl_xor_sync(~0u, t0, 1); t0 += __shfl_xor_sync(~0u, t0, 2);
    t1 += __shfl_xor_sync(~0u, t1, 1); t1 += __shfl_xor_sync(~0u, t1, 2);
    float inv0 = 1.0f / t0, inv1 = 1.0f / t1;

    // ---- P in A-fragment layout directly (acc pairs == a-frag pairs) ----
    uint32_t pa0 = bf2(s0[0] * inv0, s0[1] * inv0);   // P[i0][j 0-7]
    uint32_t pa1 = bf2(s0[2] * inv1, s0[3] * inv1);   // P[i1][j 0-7]
    uint32_t pa2 = bf2(s1[0] * inv0, s1[1] * inv0);   // P[i0][j 8-15]
    uint32_t pa3 = bf2(s1[2] * inv1, s1[3] * inv1);   // P[i1][j 8-15]

    // ---- O = P V : one k16 MMA per 8-col tile of hd=64 ----
    bf16* ob = g_ow + (size_t)(win * 16) * CDIM + head * 64;
    #pragma unroll
    for (int nt = 0; nt < 8; nt++) {
        float o[4] = {0, 0, 0, 0};
        hmma_bf16(o, pa0, pa1, pa2, pa3, vb0[nt], vb1[nt]);
        int col = nt * 8 + 2 * rlo;
        *(uint32_t*)(ob + (size_t)i0 * CDIM + col) = bf2(o[0], o[1]);
        *(uint32_t*)(ob + (size_t)i1 * CDIM + col) = bf2(o[2], o[3]);
    }
}

// ---------------------------------------------------------------------------
// Launch
// ---------------------------------------------------------------------------
extern "C" void kernel_launch(void* const* d_in, const int* in_sizes, int n_in,
                              void* d_out, int out_size)
{
    const float* x      = (const float*)d_in[0];
    const float* g1     = (const float*)d_in[1];
    const float* beta1  = (const float*)d_in[2];
    const float* w_qkv  = (const float*)d_in[3];
    const float* b_qkv  = (const float*)d_in[4];
    const float* rpb    = (const float*)d_in[5];
    const float* w_proj = (const float*)d_in[6];
    const float* b_proj = (const float*)d_in[7];
    const float* g2     = (const float*)d_in[8];
    const float* beta2  = (const float*)d_in[9];
    const float* w1     = (const float*)d_in[10];
    const float* b1     = (const float*)d_in[11];
    const float* w2     = (const float*)d_in[12];
    const float* b2     = (const float*)d_in[13];
    float* out = (float*)d_out;

    bf16 *xw, *qkv, *ow, *h2, *m1, *wq, *wp, *wa, *wb;
    float *x2;
    cudaGetSymbolAddress((void**)&xw,  g_xw);
    cudaGetSymbolAddress((void**)&qkv, g_qkv);
    cudaGetSymbolAddress((void**)&ow,  g_ow);
    cudaGetSymbolAddress((void**)&x2,  g_x2);
    cudaGetSymbolAddress((void**)&h2,  g_h2);
    cudaGetSymbolAddress((void**)&m1,  g_m1);
    cudaGetSymbolAddress((void**)&wq,  g_wqkv);
    cudaGetSymbolAddress((void**)&wp,  g_wproj);
    cudaGetSymbolAddress((void**)&wa,  g_w1);
    cudaGetSymbolAddress((void**)&wb,  g_w2);

    cudaFuncSetAttribute(mma_gemm<0>, cudaFuncAttributeMaxDynamicSharedMemorySize, DYN_BYTES);
    cudaFuncSetAttribute(mma_gemm<1>, cudaFuncAttributeMaxDynamicSharedMemorySize, DYN_BYTES);
    cudaFuncSetAttribute(mma_gemm<2>, cudaFuncAttributeMaxDynamicSharedMemorySize, DYN_BYTES);
    cudaFuncSetAttribute(mma_gemm<3>, cudaFuncAttributeMaxDynamicSharedMemorySize, DYN_BYTES);

    // 0. weights -> bf16
    round_w_kernel<<<592, 256>>>(w_qkv, w_proj, w1, w2);

    // 1. LN1 + shift + window partition -> g_xw (bf16)
    ln_kernel<true><<<ROWS, 128>>>(x, g1, beta1, xw);

    // 2. QKV: [32768,1536] = xw @ wqkv^T  (bf16 out)
    mma_gemm<0><<<dim3(1536/BN, ROWS/BM), 128, DYN_BYTES>>>(xw, wq, b_qkv, nullptr, qkv, 1536, 512);

    // 3. attention -> g_ow (bf16)
    attn_mma<<<NWINDOWS, 256>>>(rpb);

    // 4. proj + window reverse + unshift + residual(x) -> g_x2 (fp32)
    mma_gemm<3><<<dim3(512/BN, ROWS/BM), 128, DYN_BYTES>>>(ow, wp, b_proj, x, x2, 512, 512);

    // 5. LN2 -> g_h2 (bf16)
    ln_kernel<false><<<ROWS, 128>>>(x2, g2, beta2, h2);

    // 6. FC1 + GELU -> g_m1 (bf16)
    mma_gemm<1><<<dim3(1024/BN, ROWS/BM), 128, DYN_BYTES>>>(h2, wa, b1, nullptr, m1, 1024, 512);

    // 7. FC2 + residual(g_x2) -> out (fp32)
    mma_gemm<2><<<dim3(512/BN, ROWS/BM), 128, DYN_BYTES>>>(m1, wb, b2, x2, out, 512, 1024);
}